// round 12
// baseline (speedup 1.0000x reference)
#include <cuda_runtime.h>
#include <cstdint>
#include <cstddef>

#define D        128
#define DOUT     64
#define NN_MAX   100000
#define NE_MAX   1600000
#define L_MAX    3
#define KMAX     (L_MAX + 1)
#define SCAN_BLK 1024
#define NB_MAX   ((NN_MAX + SCAN_BLK - 1) / SCAN_BLK)

// ---------------- scratch (static device globals; no allocation) ----------------
__device__ __align__(256) float g_V [L_MAX][(size_t)NN_MAX * DOUT];
__device__ __align__(256) float g_d1[NN_MAX];
__device__ __align__(256) float g_d2[NN_MAX];
__device__ __align__(256) float g_Ma[KMAX][D * D];
__device__ __align__(256) float g_Mb[KMAX][D * D];
__device__ __align__(256) float g_bA[KMAX][D];
__device__ __align__(256) float g_bB[KMAX][D];
__device__ __align__(256) float g_C [KMAX][D * DOUT];
__device__ __align__(256) float g_gc[DOUT];
__device__ __align__(256) float g_g1[DOUT];
__device__ __align__(256) float g_g2[DOUT];
__device__ __align__(256) int   g_src [NE_MAX];
__device__ __align__(256) int   g_dst [NE_MAX];
__device__ __align__(256) int   g_csr [NE_MAX];
__device__ __align__(256) int   g_ptr [NN_MAX + 1];
__device__ __align__(256) int   g_cur [NN_MAX];
__device__ __align__(256) int   g_cnt [NN_MAX];
__device__ __align__(256) int   g_bsum[NB_MAX];
__device__ int g_is64;

// ---------------- f32x2 packed-FMA helpers (Blackwell FFMA2) ----------------
__device__ __forceinline__ unsigned long long pack2(float lo, float hi) {
    unsigned long long r;
    asm("mov.b64 %0, {%1, %2};" : "=l"(r) : "f"(lo), "f"(hi));
    return r;
}
__device__ __forceinline__ void unpack2(unsigned long long v, float& lo, float& hi) {
    asm("mov.b64 {%0, %1}, %2;" : "=f"(lo), "=f"(hi) : "l"(v));
}
__device__ __forceinline__ void fma2(unsigned long long& acc, unsigned long long a,
                                     unsigned long long b) {
    asm("fma.rn.f32x2 %0, %1, %2, %0;" : "+l"(acc) : "l"(a), "l"(b));
}

// ---------------- fused setup: zero_cnt blocks | init_M blocks | detect block ----------------
__global__ void k_setup(const int* __restrict__ ei32, int n32, int M) {
    int b = blockIdx.x;
    int nz = (M + 255) / 256;
    int tot = KMAX * D * D;
    int ni = (tot + KMAX * D + 255) / 256;

    if (b < nz) {                                    // zero dst histogram
        int i = b * 256 + threadIdx.x;
        if (i < M) g_cnt[i] = 0;
        return;
    }
    b -= nz;
    if (b < ni) {                                    // init M_{0,0}=I, beta=0
        int i = b * 256 + threadIdx.x;
        if (i < tot) {
            int k = i / (D * D);
            int r = i % (D * D);
            ((float*)g_Ma)[i] = (k == 0 && (r / D) == (r % D)) ? 1.f : 0.f;
        } else if (i < tot + KMAX * D) {
            ((float*)g_bA)[i - tot] = 0.f;
        }
        return;
    }
    // detect int64 vs int32 edge_index
    __shared__ int any;
    if (threadIdx.x == 0) any = 0;
    __syncthreads();
    for (int i = threadIdx.x; i < 2048; i += blockDim.x) {
        int idx = 2 * i + 1;
        if (idx < n32 && ei32[idx] != 0) any = 1;
    }
    __syncthreads();
    if (threadIdx.x == 0) g_is64 = (any == 0) ? 1 : 0;
}

__global__ void k_prep_edges(const int* __restrict__ ei32, int nE, int M) {
    int i = blockIdx.x * blockDim.x + threadIdx.x;
    if (i >= nE) return;
    int s, d;
    if (g_is64) {
        const long long* e = (const long long*)ei32;
        s = (int)e[i];
        d = (int)e[i + (size_t)nE];
    } else {
        s = ei32[i];
        d = ei32[i + (size_t)nE];
    }
    if (s < 0) s = 0; if (s >= M) s = M - 1;
    if (d < 0) d = 0; if (d >= M) d = M - 1;
    g_src[i] = s;
    g_dst[i] = d;
    atomicAdd(&g_cnt[d], 1);
}

// ---------------- CSR build ----------------
__global__ void k_scan1(int M) {
    __shared__ int sh[SCAN_BLK];
    int i = blockIdx.x * SCAN_BLK + threadIdx.x;
    int v = (i < M) ? g_cnt[i] : 0;
    sh[threadIdx.x] = v;
    __syncthreads();
#pragma unroll
    for (int off = 1; off < SCAN_BLK; off <<= 1) {
        int t = (threadIdx.x >= off) ? sh[threadIdx.x - off] : 0;
        __syncthreads();
        sh[threadIdx.x] += t;
        __syncthreads();
    }
    if (i < M) g_ptr[i] = sh[threadIdx.x] - v;
    if (threadIdx.x == SCAN_BLK - 1) g_bsum[blockIdx.x] = sh[threadIdx.x];
}

__global__ void k_scan2(int nB) {
    __shared__ int sh[128];
    int v = (threadIdx.x < nB) ? g_bsum[threadIdx.x] : 0;
    sh[threadIdx.x] = v;
    __syncthreads();
#pragma unroll
    for (int off = 1; off < 128; off <<= 1) {
        int t = (threadIdx.x >= off) ? sh[threadIdx.x - off] : 0;
        __syncthreads();
        sh[threadIdx.x] += t;
        __syncthreads();
    }
    if (threadIdx.x < nB) g_bsum[threadIdx.x] = sh[threadIdx.x] - v;
}

__global__ void k_scan3(int M, int nE) {
    int i = blockIdx.x * blockDim.x + threadIdx.x;
    if (i < M) {
        int p = g_ptr[i] + g_bsum[i / SCAN_BLK];
        g_ptr[i] = p;
        g_cur[i] = p;
        g_d1[i] = (float)g_cnt[i];
    }
    if (i == 0) g_ptr[M] = nE;
}

__global__ void k_fill(int nE) {
    int i = blockIdx.x * blockDim.x + threadIdx.x;
    if (i >= nE) return;
    int slot = atomicAdd(&g_cur[g_dst[i]], 1);
    g_csr[slot] = g_src[i];
}

__global__ void k_d2(int M) {
    int i = blockIdx.x * blockDim.x + threadIdx.x;
    if (i >= M) return;
    int beg = g_ptr[i], end = g_ptr[i + 1];
    float s = 0.f;
    int e = beg;
    for (; e + 4 <= end; e += 4) {
        float a = g_d1[g_csr[e + 0]];
        float b = g_d1[g_csr[e + 1]];
        float c = g_d1[g_csr[e + 2]];
        float d = g_d1[g_csr[e + 3]];
        s += (a + b) + (c + d);
    }
    for (; e < end; ++e) s += g_d1[g_csr[e]];
    g_d2[i] = s;
}

// ---------------- weight recurrence: stage + fused beta ----------------
// grid (9, l+1): blockIdx.x<8 -> M-stage tiles; blockIdx.x==8,y==0 -> beta.
__global__ __launch_bounds__(256) void k_stage(
    const float* __restrict__ Min, float* __restrict__ Mout,
    const float* __restrict__ Wr, const float* __restrict__ Wt, int l,
    const float* __restrict__ bin, float* __restrict__ bout,
    const float* __restrict__ bl)
{
    const int tid = threadIdx.x;

    if (blockIdx.x == 8) {
        if (blockIdx.y != 0) return;
        // ---- beta: bout_k = Wt @ bin_k + Wr @ bin_{k-1} (+ bl if k==0) ----
        __shared__ float sb[L_MAX + 1][D];
        int n = tid;
        if (n < D) {
#pragma unroll
            for (int k = 0; k < L_MAX; ++k)
                sb[k][n] = (k <= l - 2) ? bin[k * D + n] : 0.f;
            sb[L_MAX][n] = 0.f;
        }
        __syncthreads();
        if (n < D) {
            for (int k = 0; k < l; ++k) {
                const float* tp = sb[k];
                const float* rp = (k >= 1) ? sb[k - 1] : sb[L_MAX];
                float acc = (k == 0) ? bl[n] : 0.f;
#pragma unroll 4
                for (int q4 = 0; q4 < 32; ++q4) {
                    float4 wt = *(const float4*)&Wt[(size_t)n * D + q4 * 4];
                    float4 wr = *(const float4*)&Wr[(size_t)n * D + q4 * 4];
                    acc += wt.x * tp[q4 * 4 + 0] + wt.y * tp[q4 * 4 + 1]
                         + wt.z * tp[q4 * 4 + 2] + wt.w * tp[q4 * 4 + 3]
                         + wr.x * rp[q4 * 4 + 0] + wr.y * rp[q4 * 4 + 1]
                         + wr.z * rp[q4 * 4 + 2] + wr.w * rp[q4 * 4 + 3];
                }
                bout[k * D + n] = acc;
            }
        }
        return;
    }

    // ---- M stage: Mout_k = Min_k @ Wt^T + Min_{k-1} @ Wr^T ----
    __shared__ float sT[32][132];
    __shared__ float sR[32][132];
    __shared__ float sWt[64][16];
    __shared__ float sWr[64][16];

    const int k   = blockIdx.y;
    const int p0  = (blockIdx.x >> 1) * 32;
    const int nh  = (blockIdx.x & 1) * 64;

    const bool vT = (k <= l - 1);
    const bool vR = (k >= 1);
    for (int i = tid * 4; i < 32 * 128; i += 1024) {
        int p = i >> 7, q = i & 127;
        float4 t = vT ? *(const float4*)&Min[(size_t)k * D * D + (p0 + p) * D + q]
                      : make_float4(0.f, 0.f, 0.f, 0.f);
        float4 r = vR ? *(const float4*)&Min[(size_t)(k - 1) * D * D + (p0 + p) * D + q]
                      : make_float4(0.f, 0.f, 0.f, 0.f);
        *(float4*)&sT[p][q] = t;
        *(float4*)&sR[p][q] = r;
    }

    const int p  = tid & 31;
    const int nl = (tid >> 5) * 8;
    const int wn = (tid * 4) >> 4;        // W loader row
    const int wq = (tid * 4) & 15;        // W loader col
    float acc[8] = {0.f, 0.f, 0.f, 0.f, 0.f, 0.f, 0.f, 0.f};

    // register double-buffer for W tiles
    float4 wtp = *(const float4*)&Wt[(size_t)(nh + wn) * D + 0 + wq];
    float4 wrp = *(const float4*)&Wr[(size_t)(nh + wn) * D + 0 + wq];

#pragma unroll 1
    for (int qt = 0; qt < 8; ++qt) {
        int q0 = qt * 16;
        __syncthreads();
        *(float4*)&sWt[wn][wq] = wtp;
        *(float4*)&sWr[wn][wq] = wrp;
        __syncthreads();
        if (qt + 1 < 8) {
            int qn = (qt + 1) * 16;
            wtp = *(const float4*)&Wt[(size_t)(nh + wn) * D + qn + wq];
            wrp = *(const float4*)&Wr[(size_t)(nh + wn) * D + qn + wq];
        }
#pragma unroll
        for (int q4 = 0; q4 < 4; ++q4) {
            float4 t = *(const float4*)&sT[p][q0 + q4 * 4];
            float4 r = *(const float4*)&sR[p][q0 + q4 * 4];
#pragma unroll
            for (int n = 0; n < 8; ++n) {
                float4 wt = *(const float4*)&sWt[nl + n][q4 * 4];
                float4 wr = *(const float4*)&sWr[nl + n][q4 * 4];
                acc[n] += t.x * wt.x + t.y * wt.y + t.z * wt.z + t.w * wt.w
                        + r.x * wr.x + r.y * wr.y + r.z * wr.z + r.w * wr.w;
            }
        }
    }

#pragma unroll
    for (int n = 0; n < 8; ++n)
        Mout[(size_t)k * D * D + (p0 + p) * D + (nh + nl + n)] = acc[n];
}

// ---------------- C_k = M3_k @ fc_w^T, with fused gamma block ----------------
// grid (5, KMAX): x<4 -> C tiles; x==4,y==0 -> gamma.
__global__ __launch_bounds__(256) void k_make_C(const float* __restrict__ M3,
                                                const float* __restrict__ fcw,
                                                const float* __restrict__ b3,
                                                const float* __restrict__ fcb, int L) {
    const int tid = threadIdx.x;

    if (blockIdx.x == 4) {
        if (blockIdx.y != 0 || tid >= DOUT) return;
        int n = tid;
        float a0 = fcb[n], a1 = 0.f, a2 = 0.f;
#pragma unroll 4
        for (int q4 = 0; q4 < 32; ++q4) {
            float4 w = *(const float4*)&fcw[(size_t)n * D + q4 * 4];
            float4 v0 = *(const float4*)&b3[0 * D + q4 * 4];
            a0 += w.x * v0.x + w.y * v0.y + w.z * v0.z + w.w * v0.w;
            if (L >= 2) {
                float4 v1 = *(const float4*)&b3[1 * D + q4 * 4];
                a1 += w.x * v1.x + w.y * v1.y + w.z * v1.z + w.w * v1.w;
            }
            if (L >= 3) {
                float4 v2 = *(const float4*)&b3[2 * D + q4 * 4];
                a2 += w.x * v2.x + w.y * v2.y + w.z * v2.z + w.w * v2.w;
            }
        }
        g_gc[n] = a0; g_g1[n] = a1; g_g2[n] = a2;
        return;
    }

    __shared__ float sM[32][132];
    __shared__ float sW[64][16];
    const int k   = blockIdx.y;
    const int p0  = blockIdx.x * 32;

    for (int i = tid * 4; i < 32 * 128; i += 1024) {
        int p = i >> 7, q = i & 127;
        *(float4*)&sM[p][q] = *(const float4*)&M3[(size_t)k * D * D + (p0 + p) * D + q];
    }

    const int p  = tid & 31;
    const int nl = (tid >> 5) * 8;
    const int wn = (tid * 4) >> 4;
    const int wq = (tid * 4) & 15;
    float acc[8] = {0.f, 0.f, 0.f, 0.f, 0.f, 0.f, 0.f, 0.f};

    float4 wp = *(const float4*)&fcw[(size_t)wn * D + 0 + wq];

#pragma unroll 1
    for (int qt = 0; qt < 8; ++qt) {
        int q0 = qt * 16;
        __syncthreads();
        *(float4*)&sW[wn][wq] = wp;
        __syncthreads();
        if (qt + 1 < 8) {
            int qn = (qt + 1) * 16;
            wp = *(const float4*)&fcw[(size_t)wn * D + qn + wq];
        }
#pragma unroll
        for (int q4 = 0; q4 < 4; ++q4) {
            float4 m = *(const float4*)&sM[p][q0 + q4 * 4];
#pragma unroll
            for (int n = 0; n < 8; ++n) {
                float4 w = *(const float4*)&sW[nl + n][q4 * 4];
                acc[n] += m.x * w.x + m.y * w.y + m.z * w.z + m.w * w.w;
            }
        }
    }
#pragma unroll
    for (int n = 0; n < 8; ++n)
        g_C[k][(p0 + p) * DOUT + nl + n] = acc[n];
}

// ---------------- projection GEMM: V_k = x0 @ C_k (+ bias terms for k==0) ----------------
// BM=128, BN=64, full-K B in smem, 256 threads, thread tile 8 rows x 4 cols.
// Row-paired f32x2 accumulators: A pairs come packed from As for free (0 movs);
// only B needs 4 dup-movs per k.  acc[rp][c] = rows (trow*8+2rp, +1), col tcol*4+c.
__global__ __launch_bounds__(256, 2) void k_gemm_proj(
    const float* __restrict__ A, const float* __restrict__ d1,
    const float* __restrict__ d2, float* __restrict__ out, int M)
{
    __shared__ __align__(16) float Bs[D * DOUT];
    __shared__ __align__(16) float As[8][128];

    const int kk = blockIdx.y;
    float* O = (kk == 0) ? out : &g_V[kk - 1][0];
    const float* B = &g_C[kk][0];

    const int tid  = threadIdx.x;
    const int trow = tid >> 4;
    const int tcol = tid & 15;
    const int block_row = blockIdx.x * 128;

#pragma unroll
    for (int v = 0; v < 8; ++v) {
        int o = v * 1024 + tid * 4;
        *(float4*)&Bs[o] = *(const float4*)&B[o];
    }

    const int arow = tid >> 1;
    const int akk  = (tid & 1) << 2;
    int grow = block_row + arow;
    if (grow >= M) grow = M - 1;

    unsigned long long acc[4][4];   // [row-pair][col]
#pragma unroll
    for (int i = 0; i < 4; i++)
#pragma unroll
        for (int j = 0; j < 4; j++) acc[i][j] = 0ull;

    float4 aref = *(const float4*)(A + (size_t)grow * D + akk);
    __syncthreads();

#pragma unroll 1
    for (int s = 0; s < 16; ++s) {
        As[akk + 0][arow] = aref.x;
        As[akk + 1][arow] = aref.y;
        As[akk + 2][arow] = aref.z;
        As[akk + 3][arow] = aref.w;
        __syncthreads();

        if (s + 1 < 16) {
            int kb = (s + 1) * 8;
            aref = *(const float4*)(A + (size_t)grow * D + kb + akk);
        }

        int k0 = s * 8;
#pragma unroll
        for (int k = 0; k < 8; ++k) {
            // packed row-pairs directly from shared (no movs)
            ulonglong2 a01 = *(const ulonglong2*)&As[k][trow * 8];
            ulonglong2 a23 = *(const ulonglong2*)&As[k][trow * 8 + 4];
            float4 b = *(const float4*)&Bs[(k0 + k) * DOUT + tcol * 4];
            unsigned long long b0 = pack2(b.x, b.x);
            unsigned long long b1 = pack2(b.y, b.y);
            unsigned long long b2 = pack2(b.z, b.z);
            unsigned long long b3 = pack2(b.w, b.w);
            fma2(acc[0][0], a01.x, b0); fma2(acc[0][1], a01.x, b1);
            fma2(acc[0][2], a01.x, b2); fma2(acc[0][3], a01.x, b3);
            fma2(acc[1][0], a01.y, b0); fma2(acc[1][1], a01.y, b1);
            fma2(acc[1][2], a01.y, b2); fma2(acc[1][3], a01.y, b3);
            fma2(acc[2][0], a23.x, b0); fma2(acc[2][1], a23.x, b1);
            fma2(acc[2][2], a23.x, b2); fma2(acc[2][3], a23.x, b3);
            fma2(acc[3][0], a23.y, b0); fma2(acc[3][1], a23.y, b1);
            fma2(acc[3][2], a23.y, b2); fma2(acc[3][3], a23.y, b3);
        }
        __syncthreads();
    }

#pragma unroll
    for (int rp = 0; rp < 4; ++rp) {
        float lo0, hi0, lo1, hi1, lo2, hi2, lo3, hi3;
        unpack2(acc[rp][0], lo0, hi0);
        unpack2(acc[rp][1], lo1, hi1);
        unpack2(acc[rp][2], lo2, hi2);
        unpack2(acc[rp][3], lo3, hi3);
        int r0 = block_row + trow * 8 + 2 * rp;
        int c  = tcol * 4;
        if (r0 < M) {
            float v0 = lo0, v1 = lo1, v2 = lo2, v3 = lo3;
            if (kk == 0) {
                float dd1 = d1[r0], dd2 = d2[r0];
                v0 += g_gc[c + 0] + dd1 * g_g1[c + 0] + dd2 * g_g2[c + 0];
                v1 += g_gc[c + 1] + dd1 * g_g1[c + 1] + dd2 * g_g2[c + 1];
                v2 += g_gc[c + 2] + dd1 * g_g1[c + 2] + dd2 * g_g2[c + 2];
                v3 += g_gc[c + 3] + dd1 * g_g1[c + 3] + dd2 * g_g2[c + 3];
            }
            *(float4*)(O + (size_t)r0 * DOUT + c) = make_float4(v0, v1, v2, v3);
        }
        if (r0 + 1 < M) {
            float v0 = hi0, v1 = hi1, v2 = hi2, v3 = hi3;
            if (kk == 0) {
                float dd1 = d1[r0 + 1], dd2 = d2[r0 + 1];
                v0 += g_gc[c + 0] + dd1 * g_g1[c + 0] + dd2 * g_g2[c + 0];
                v1 += g_gc[c + 1] + dd1 * g_g1[c + 1] + dd2 * g_g2[c + 1];
                v2 += g_gc[c + 2] + dd1 * g_g1[c + 2] + dd2 * g_g2[c + 2];
                v3 += g_gc[c + 3] + dd1 * g_g1[c + 3] + dd2 * g_g2[c + 3];
            }
            *(float4*)(O + (size_t)(r0 + 1) * DOUT + c) = make_float4(v0, v1, v2, v3);
        }
    }
}

// ---------------- CSR gather-aggregation: dst[i] += sum_{j in N(i)} src[j] ----------------
__global__ __launch_bounds__(256) void k_agg(const float* __restrict__ src,
                                             float* __restrict__ dst, int M) {
    int node = blockIdx.x * 16 + (threadIdx.x >> 4);
    int l16  = threadIdx.x & 15;
    if (node >= M) return;
    int beg = g_ptr[node], end = g_ptr[node + 1];

    float4 acc = *(const float4*)(dst + (size_t)node * DOUT + l16 * 4);

    int e = beg;
    for (; e + 4 <= end; e += 4) {
        int s0 = g_csr[e], s1 = g_csr[e + 1], s2 = g_csr[e + 2], s3 = g_csr[e + 3];
        float4 v0 = *(const float4*)(src + (size_t)s0 * DOUT + l16 * 4);
        float4 v1 = *(const float4*)(src + (size_t)s1 * DOUT + l16 * 4);
        float4 v2 = *(const float4*)(src + (size_t)s2 * DOUT + l16 * 4);
        float4 v3 = *(const float4*)(src + (size_t)s3 * DOUT + l16 * 4);
        acc.x += (v0.x + v1.x) + (v2.x + v3.x);
        acc.y += (v0.y + v1.y) + (v2.y + v3.y);
        acc.z += (v0.z + v1.z) + (v2.z + v3.z);
        acc.w += (v0.w + v1.w) + (v2.w + v3.w);
    }
    for (; e < end; ++e) {
        int s0 = g_csr[e];
        float4 v0 = *(const float4*)(src + (size_t)s0 * DOUT + l16 * 4);
        acc.x += v0.x; acc.y += v0.y; acc.z += v0.z; acc.w += v0.w;
    }
    *(float4*)(dst + (size_t)node * DOUT + l16 * 4) = acc;
}

// ---------------- host orchestration ----------------
extern "C" void kernel_launch(void* const* d_in, const int* in_sizes, int n_in,
                              void* d_out, int out_size)
{
    const float* x      = (const float*)d_in[0];
    const int*   ei32   = (const int*)d_in[1];
    const float* W_rel  = (const float*)d_in[2];
    const float* b_rel  = (const float*)d_in[3];
    const float* W_root = (const float*)d_in[4];
    const float* fc_w   = (const float*)d_in[5];
    const float* fc_b   = (const float*)d_in[6];
    float*       out    = (float*)d_out;

    int M  = in_sizes[0] / D;
    int nE = in_sizes[1] / 2;
    int L  = in_sizes[2] / (D * D);
    if (M > NN_MAX) M = NN_MAX;
    if (nE > NE_MAX) nE = NE_MAX;
    if (L > L_MAX) L = L_MAX;

    float *Ma, *Mb, *bA, *bB, *Vbase, *d1, *d2;
    cudaGetSymbolAddress((void**)&Ma, g_Ma);
    cudaGetSymbolAddress((void**)&Mb, g_Mb);
    cudaGetSymbolAddress((void**)&bA, g_bA);
    cudaGetSymbolAddress((void**)&bB, g_bB);
    cudaGetSymbolAddress((void**)&Vbase, g_V);
    cudaGetSymbolAddress((void**)&d1, g_d1);
    cudaGetSymbolAddress((void**)&d2, g_d2);

    // fused setup: zero_cnt | init_M | detect
    int nz = (M + 255) / 256;
    int ni = (KMAX * D * D + KMAX * D + 255) / 256;
    k_setup<<<nz + ni + 1, 256>>>(ei32, in_sizes[1], M);

    k_prep_edges<<<(nE + 255) / 256, 256>>>(ei32, nE, M);

    // weight recurrence (stage + fused beta), interleaved with CSR scans
    const float* Min = Ma;  float* Mout = Mb;
    const float* bin = bA;  float* bout = bB;
    int nB = (M + SCAN_BLK - 1) / SCAN_BLK;

    k_scan1<<<nB, SCAN_BLK>>>(M);
    for (int l = 1; l <= L; ++l) {
        const float* Wr = W_rel  + (size_t)(l - 1) * D * D;
        const float* Wt = W_root + (size_t)(l - 1) * D * D;
        const float* bl = b_rel  + (size_t)(l - 1) * D;
        k_stage<<<dim3(9, l + 1), 256>>>(Min, Mout, Wr, Wt, l, bin, bout, bl);
        const float* t1 = Min; Min = Mout; Mout = (float*)t1;
        const float* t2 = bin; bin = bout; bout = (float*)t2;
    }
    k_scan2<<<1, 128>>>(nB);
    k_scan3<<<(M + 255) / 256, 256>>>(M, nE);
    k_fill<<<(nE + 255) / 256, 256>>>(nE);
    k_make_C<<<dim3(5, L + 1), 256>>>(Min, fc_w, bin, fc_b, L);
    k_d2<<<(M + 255) / 256, 256>>>(M);

    // V_k = x0 @ C_k   (k=0 -> out with bias/degree epilogue)
    int gemm_blocks = (M + 127) / 128;
    k_gemm_proj<<<dim3(gemm_blocks, L + 1), 256>>>(x, d1, d2, out, M);

    // Horner: out = V0 + A(V1 + A(V2 + A V3)), CSR gather (no atomics)
    int agg_blocks = (M + 15) / 16;
    for (int k = L; k >= 1; --k) {
        const float* s = Vbase + (size_t)(k - 1) * NN_MAX * DOUT;
        float*       t = (k == 1) ? out : (Vbase + (size_t)(k - 2) * NN_MAX * DOUT);
        k_agg<<<agg_blocks, 256>>>(s, t, M);
    }
}

// round 13
// speedup vs baseline: 1.0111x; 1.0111x over previous
#include <cuda_runtime.h>
#include <cstdint>
#include <cstddef>

#define D        128
#define DOUT     64
#define NN_MAX   100000
#define NE_MAX   1600000
#define L_MAX    3
#define KMAX     (L_MAX + 1)
#define SCAN_BLK 256
#define NB_MAX   ((NN_MAX + SCAN_BLK - 1) / SCAN_BLK)   // 391

// ---------------- scratch (static device globals; no allocation) ----------------
__device__ __align__(256) float g_V [L_MAX][(size_t)NN_MAX * DOUT];
__device__ __align__(256) float g_d1[NN_MAX];
__device__ __align__(256) float g_d2[NN_MAX];
__device__ __align__(256) float g_Ma[KMAX][D * D];
__device__ __align__(256) float g_Mb[KMAX][D * D];
__device__ __align__(256) float g_bA[KMAX][D];
__device__ __align__(256) float g_bB[KMAX][D];
__device__ __align__(256) float g_C [KMAX][D * DOUT];
__device__ __align__(256) float g_gc[DOUT];
__device__ __align__(256) float g_g1[DOUT];
__device__ __align__(256) float g_g2[DOUT];
__device__ __align__(256) int   g_src [NE_MAX];
__device__ __align__(256) int   g_dst [NE_MAX];
__device__ __align__(256) int   g_csr [NE_MAX];
__device__ __align__(256) int   g_ptr [NN_MAX + 1];
__device__ __align__(256) int   g_cur [NN_MAX];
__device__ __align__(256) int   g_cnt [NN_MAX];
__device__ __align__(256) int   g_bsum[NB_MAX];
__device__ int g_is64;

// ---------------- f32x2 packed-FMA helpers (Blackwell FFMA2) ----------------
__device__ __forceinline__ unsigned long long pack2(float lo, float hi) {
    unsigned long long r;
    asm("mov.b64 %0, {%1, %2};" : "=l"(r) : "f"(lo), "f"(hi));
    return r;
}
__device__ __forceinline__ void unpack2(unsigned long long v, float& lo, float& hi) {
    asm("mov.b64 {%0, %1}, %2;" : "=f"(lo), "=f"(hi) : "l"(v));
}
__device__ __forceinline__ void fma2(unsigned long long& acc, unsigned long long a,
                                     unsigned long long b) {
    asm("fma.rn.f32x2 %0, %1, %2, %0;" : "+l"(acc) : "l"(a), "l"(b));
}

// ================= device bodies (composed by merged kernels) =================

__device__ void prep_body(int pid, const int* __restrict__ ei32, int nE, int M) {
    int i = pid * 256 + threadIdx.x;
    if (i >= nE) return;
    int s, d;
    if (g_is64) {
        const long long* e = (const long long*)ei32;
        s = (int)e[i];
        d = (int)e[i + (size_t)nE];
    } else {
        s = ei32[i];
        d = ei32[i + (size_t)nE];
    }
    if (s < 0) s = 0; if (s >= M) s = M - 1;
    if (d < 0) d = 0; if (d >= M) d = M - 1;
    g_src[i] = s;
    g_dst[i] = d;
    atomicAdd(&g_cnt[d], 1);
}

__device__ void scan1_body(int bid, int M) {
    __shared__ int sh[SCAN_BLK];
    int i = bid * SCAN_BLK + threadIdx.x;
    int v = (i < M) ? g_cnt[i] : 0;
    sh[threadIdx.x] = v;
    __syncthreads();
#pragma unroll
    for (int off = 1; off < SCAN_BLK; off <<= 1) {
        int t = (threadIdx.x >= off) ? sh[threadIdx.x - off] : 0;
        __syncthreads();
        sh[threadIdx.x] += t;
        __syncthreads();
    }
    if (i < M) g_ptr[i] = sh[threadIdx.x] - v;
    if (threadIdx.x == SCAN_BLK - 1) g_bsum[bid] = sh[threadIdx.x];
}

// single block, warp-serial scan over nB block sums (exclusive)
__device__ void scan2_body(int nB) {
    if (threadIdx.x >= 32) return;
    int lane = threadIdx.x;
    int carry = 0;
    int nCh = (nB + 31) / 32;
    for (int c = 0; c < nCh; ++c) {
        int idx = c * 32 + lane;
        int v = (idx < nB) ? g_bsum[idx] : 0;
        int incl = v;
#pragma unroll
        for (int off = 1; off < 32; off <<= 1) {
            int t = __shfl_up_sync(0xFFFFFFFFu, incl, off);
            if (lane >= off) incl += t;
        }
        int total = __shfl_sync(0xFFFFFFFFu, incl, 31);
        if (idx < nB) g_bsum[idx] = incl - v + carry;
        carry += total;
    }
}

__device__ void scan3_body(int bid, int M, int nE) {
    int i = bid * 256 + threadIdx.x;
    if (i < M) {
        int p = g_ptr[i] + g_bsum[i / SCAN_BLK];
        g_ptr[i] = p;
        g_cur[i] = p;
        g_d1[i] = (float)g_cnt[i];
    }
    if (i == 0) g_ptr[M] = nE;
}

__device__ void fill_body(int bid, int nE) {
    int i = bid * 256 + threadIdx.x;
    if (i >= nE) return;
    int slot = atomicAdd(&g_cur[g_dst[i]], 1);
    g_csr[slot] = g_src[i];
}

__device__ void d2_body(int bid, int M) {
    int i = bid * 256 + threadIdx.x;
    if (i >= M) return;
    int beg = g_ptr[i], end = g_ptr[i + 1];
    float s = 0.f;
    int e = beg;
    for (; e + 4 <= end; e += 4) {
        float a = g_d1[g_csr[e + 0]];
        float b = g_d1[g_csr[e + 1]];
        float c = g_d1[g_csr[e + 2]];
        float d = g_d1[g_csr[e + 3]];
        s += (a + b) + (c + d);
    }
    for (; e < end; ++e) s += g_d1[g_csr[e]];
    g_d2[i] = s;
}

__device__ void agg_body(int bid, const float* __restrict__ src,
                         float* __restrict__ dst, int M) {
    int node = bid * 16 + (threadIdx.x >> 4);
    int l16  = threadIdx.x & 15;
    if (node >= M) return;
    int beg = g_ptr[node], end = g_ptr[node + 1];

    float4 acc = *(const float4*)(dst + (size_t)node * DOUT + l16 * 4);
    int e = beg;
    for (; e + 4 <= end; e += 4) {
        int s0 = g_csr[e], s1 = g_csr[e + 1], s2 = g_csr[e + 2], s3 = g_csr[e + 3];
        float4 v0 = *(const float4*)(src + (size_t)s0 * DOUT + l16 * 4);
        float4 v1 = *(const float4*)(src + (size_t)s1 * DOUT + l16 * 4);
        float4 v2 = *(const float4*)(src + (size_t)s2 * DOUT + l16 * 4);
        float4 v3 = *(const float4*)(src + (size_t)s3 * DOUT + l16 * 4);
        acc.x += (v0.x + v1.x) + (v2.x + v3.x);
        acc.y += (v0.y + v1.y) + (v2.y + v3.y);
        acc.z += (v0.z + v1.z) + (v2.z + v3.z);
        acc.w += (v0.w + v1.w) + (v2.w + v3.w);
    }
    for (; e < end; ++e) {
        int s0 = g_csr[e];
        float4 v0 = *(const float4*)(src + (size_t)s0 * DOUT + l16 * 4);
        acc.x += v0.x; acc.y += v0.y; acc.z += v0.z; acc.w += v0.w;
    }
    *(float4*)(dst + (size_t)node * DOUT + l16 * 4) = acc;
}

__device__ void degadd_body(int bid, float* __restrict__ out, int M) {
    int node = bid * 16 + (threadIdx.x >> 4);
    if (node >= M) return;
    int c = (threadIdx.x & 15) * 4;
    float dd1 = g_d1[node], dd2 = g_d2[node];
    float4 o = *(float4*)(out + (size_t)node * DOUT + c);
    o.x += dd1 * g_g1[c + 0] + dd2 * g_g2[c + 0];
    o.y += dd1 * g_g1[c + 1] + dd2 * g_g2[c + 1];
    o.z += dd1 * g_g1[c + 2] + dd2 * g_g2[c + 2];
    o.w += dd1 * g_g1[c + 3] + dd2 * g_g2[c + 3];
    *(float4*)(out + (size_t)node * DOUT + c) = o;
}

// stage sb in [0, 9*(l+1)): k = sb % (l+1), sx = sb / (l+1); sx==8 -> beta (k==0 only)
__device__ void stage_body(int sb, int l,
                           const float* __restrict__ Min, float* __restrict__ Mout,
                           const float* __restrict__ Wr, const float* __restrict__ Wt,
                           const float* __restrict__ bin, float* __restrict__ bout,
                           const float* __restrict__ bl)
{
    const int tid = threadIdx.x;
    const int k   = sb % (l + 1);
    const int sx  = sb / (l + 1);

    if (sx == 8) {
        if (k != 0) return;
        __shared__ float sbeta[L_MAX + 1][D];
        int n = tid;
        if (n < D) {
#pragma unroll
            for (int kk = 0; kk < L_MAX; ++kk)
                sbeta[kk][n] = (kk <= l - 2) ? bin[kk * D + n] : 0.f;
            sbeta[L_MAX][n] = 0.f;
        }
        __syncthreads();
        if (n < D) {
            for (int kk = 0; kk < l; ++kk) {
                const float* tp = sbeta[kk];
                const float* rp = (kk >= 1) ? sbeta[kk - 1] : sbeta[L_MAX];
                float acc = (kk == 0) ? bl[n] : 0.f;
#pragma unroll 4
                for (int q4 = 0; q4 < 32; ++q4) {
                    float4 wt = *(const float4*)&Wt[(size_t)n * D + q4 * 4];
                    float4 wr = *(const float4*)&Wr[(size_t)n * D + q4 * 4];
                    acc += wt.x * tp[q4 * 4 + 0] + wt.y * tp[q4 * 4 + 1]
                         + wt.z * tp[q4 * 4 + 2] + wt.w * tp[q4 * 4 + 3]
                         + wr.x * rp[q4 * 4 + 0] + wr.y * rp[q4 * 4 + 1]
                         + wr.z * rp[q4 * 4 + 2] + wr.w * rp[q4 * 4 + 3];
                }
                bout[kk * D + n] = acc;
            }
        }
        return;
    }

    __shared__ float sT[32][132];
    __shared__ float sR[32][132];
    __shared__ float sWt[64][16];
    __shared__ float sWr[64][16];

    const int p0 = (sx >> 1) * 32;
    const int nh = (sx & 1) * 64;

    const bool vT = (k <= l - 1);
    const bool vR = (k >= 1);
    for (int i = tid * 4; i < 32 * 128; i += 1024) {
        int p = i >> 7, q = i & 127;
        float4 t = vT ? *(const float4*)&Min[(size_t)k * D * D + (p0 + p) * D + q]
                      : make_float4(0.f, 0.f, 0.f, 0.f);
        float4 r = vR ? *(const float4*)&Min[(size_t)(k - 1) * D * D + (p0 + p) * D + q]
                      : make_float4(0.f, 0.f, 0.f, 0.f);
        *(float4*)&sT[p][q] = t;
        *(float4*)&sR[p][q] = r;
    }

    const int p  = tid & 31;
    const int nl = (tid >> 5) * 8;
    const int wn = (tid * 4) >> 4;
    const int wq = (tid * 4) & 15;
    float acc[8] = {0.f, 0.f, 0.f, 0.f, 0.f, 0.f, 0.f, 0.f};

    float4 wtp = *(const float4*)&Wt[(size_t)(nh + wn) * D + 0 + wq];
    float4 wrp = *(const float4*)&Wr[(size_t)(nh + wn) * D + 0 + wq];

#pragma unroll 1
    for (int qt = 0; qt < 8; ++qt) {
        int q0 = qt * 16;
        __syncthreads();
        *(float4*)&sWt[wn][wq] = wtp;
        *(float4*)&sWr[wn][wq] = wrp;
        __syncthreads();
        if (qt + 1 < 8) {
            int qn = (qt + 1) * 16;
            wtp = *(const float4*)&Wt[(size_t)(nh + wn) * D + qn + wq];
            wrp = *(const float4*)&Wr[(size_t)(nh + wn) * D + qn + wq];
        }
#pragma unroll
        for (int q4 = 0; q4 < 4; ++q4) {
            float4 t = *(const float4*)&sT[p][q0 + q4 * 4];
            float4 r = *(const float4*)&sR[p][q0 + q4 * 4];
#pragma unroll
            for (int n = 0; n < 8; ++n) {
                float4 wt = *(const float4*)&sWt[nl + n][q4 * 4];
                float4 wr = *(const float4*)&sWr[nl + n][q4 * 4];
                acc[n] += t.x * wt.x + t.y * wt.y + t.z * wt.z + t.w * wt.w
                        + r.x * wr.x + r.y * wr.y + r.z * wr.z + r.w * wr.w;
            }
        }
    }

#pragma unroll
    for (int n = 0; n < 8; ++n)
        Mout[(size_t)k * D * D + (p0 + p) * D + (nh + nl + n)] = acc[n];
}

// makeC sb in [0, 5*(L+1)): ky = sb % (L+1), bx = sb / (L+1); bx==4 -> gamma (ky==0)
__device__ void makeC_body(int sb, int L,
                           const float* __restrict__ M3, const float* __restrict__ fcw,
                           const float* __restrict__ b3, const float* __restrict__ fcb)
{
    const int tid = threadIdx.x;
    const int ky  = sb % (L + 1);
    const int bx  = sb / (L + 1);

    if (bx == 4) {
        if (ky != 0 || tid >= DOUT) return;
        int n = tid;
        float a0 = fcb[n], a1 = 0.f, a2 = 0.f;
#pragma unroll 4
        for (int q4 = 0; q4 < 32; ++q4) {
            float4 w = *(const float4*)&fcw[(size_t)n * D + q4 * 4];
            float4 v0 = *(const float4*)&b3[0 * D + q4 * 4];
            a0 += w.x * v0.x + w.y * v0.y + w.z * v0.z + w.w * v0.w;
            if (L >= 2) {
                float4 v1 = *(const float4*)&b3[1 * D + q4 * 4];
                a1 += w.x * v1.x + w.y * v1.y + w.z * v1.z + w.w * v1.w;
            }
            if (L >= 3) {
                float4 v2 = *(const float4*)&b3[2 * D + q4 * 4];
                a2 += w.x * v2.x + w.y * v2.y + w.z * v2.z + w.w * v2.w;
            }
        }
        g_gc[n] = a0; g_g1[n] = a1; g_g2[n] = a2;
        return;
    }

    __shared__ float sM[32][132];
    __shared__ float sW[64][16];
    const int k  = ky;
    const int p0 = bx * 32;

    for (int i = tid * 4; i < 32 * 128; i += 1024) {
        int p = i >> 7, q = i & 127;
        *(float4*)&sM[p][q] = *(const float4*)&M3[(size_t)k * D * D + (p0 + p) * D + q];
    }

    const int p  = tid & 31;
    const int nl = (tid >> 5) * 8;
    const int wn = (tid * 4) >> 4;
    const int wq = (tid * 4) & 15;
    float acc[8] = {0.f, 0.f, 0.f, 0.f, 0.f, 0.f, 0.f, 0.f};

    float4 wp = *(const float4*)&fcw[(size_t)wn * D + 0 + wq];

#pragma unroll 1
    for (int qt = 0; qt < 8; ++qt) {
        int q0 = qt * 16;
        __syncthreads();
        *(float4*)&sW[wn][wq] = wp;
        __syncthreads();
        if (qt + 1 < 8) {
            int qn = (qt + 1) * 16;
            wp = *(const float4*)&fcw[(size_t)wn * D + qn + wq];
        }
#pragma unroll
        for (int q4 = 0; q4 < 4; ++q4) {
            float4 m = *(const float4*)&sM[p][q0 + q4 * 4];
#pragma unroll
            for (int n = 0; n < 8; ++n) {
                float4 w = *(const float4*)&sW[nl + n][q4 * 4];
                acc[n] += m.x * w.x + m.y * w.y + m.z * w.z + m.w * w.w;
            }
        }
    }
#pragma unroll
    for (int n = 0; n < 8; ++n)
        g_C[k][(p0 + p) * DOUT + nl + n] = acc[n];
}

// projection tile: row-paired f32x2 accumulators (R11); kk==0 adds g_gc only
__device__ void proj_body(int tile, int kk, const float* __restrict__ A,
                          float* __restrict__ out, int M)
{
    __shared__ __align__(16) float Bs[D * DOUT];
    __shared__ __align__(16) float As[8][128];

    float* O = (kk == 0) ? out : &g_V[kk - 1][0];
    const float* B = &g_C[kk][0];

    const int tid  = threadIdx.x;
    const int trow = tid >> 4;
    const int tcol = tid & 15;
    const int block_row = tile * 128;

#pragma unroll
    for (int v = 0; v < 8; ++v) {
        int o = v * 1024 + tid * 4;
        *(float4*)&Bs[o] = *(const float4*)&B[o];
    }

    const int arow = tid >> 1;
    const int akk  = (tid & 1) << 2;
    int grow = block_row + arow;
    if (grow >= M) grow = M - 1;

    unsigned long long acc[4][4];
#pragma unroll
    for (int i = 0; i < 4; i++)
#pragma unroll
        for (int j = 0; j < 4; j++) acc[i][j] = 0ull;

    float4 aref = *(const float4*)(A + (size_t)grow * D + akk);
    __syncthreads();

#pragma unroll 1
    for (int s = 0; s < 16; ++s) {
        As[akk + 0][arow] = aref.x;
        As[akk + 1][arow] = aref.y;
        As[akk + 2][arow] = aref.z;
        As[akk + 3][arow] = aref.w;
        __syncthreads();

        if (s + 1 < 16) {
            int kb = (s + 1) * 8;
            aref = *(const float4*)(A + (size_t)grow * D + kb + akk);
        }

        int k0 = s * 8;
#pragma unroll
        for (int k = 0; k < 8; ++k) {
            ulonglong2 a01 = *(const ulonglong2*)&As[k][trow * 8];
            ulonglong2 a23 = *(const ulonglong2*)&As[k][trow * 8 + 4];
            float4 b = *(const float4*)&Bs[(k0 + k) * DOUT + tcol * 4];
            unsigned long long b0 = pack2(b.x, b.x);
            unsigned long long b1 = pack2(b.y, b.y);
            unsigned long long b2 = pack2(b.z, b.z);
            unsigned long long b3 = pack2(b.w, b.w);
            fma2(acc[0][0], a01.x, b0); fma2(acc[0][1], a01.x, b1);
            fma2(acc[0][2], a01.x, b2); fma2(acc[0][3], a01.x, b3);
            fma2(acc[1][0], a01.y, b0); fma2(acc[1][1], a01.y, b1);
            fma2(acc[1][2], a01.y, b2); fma2(acc[1][3], a01.y, b3);
            fma2(acc[2][0], a23.x, b0); fma2(acc[2][1], a23.x, b1);
            fma2(acc[2][2], a23.x, b2); fma2(acc[2][3], a23.x, b3);
            fma2(acc[3][0], a23.y, b0); fma2(acc[3][1], a23.y, b1);
            fma2(acc[3][2], a23.y, b2); fma2(acc[3][3], a23.y, b3);
        }
        __syncthreads();
    }

#pragma unroll
    for (int rp = 0; rp < 4; ++rp) {
        float lo0, hi0, lo1, hi1, lo2, hi2, lo3, hi3;
        unpack2(acc[rp][0], lo0, hi0);
        unpack2(acc[rp][1], lo1, hi1);
        unpack2(acc[rp][2], lo2, hi2);
        unpack2(acc[rp][3], lo3, hi3);
        int r0 = block_row + trow * 8 + 2 * rp;
        int c  = tcol * 4;
        if (r0 < M) {
            float v0 = lo0, v1 = lo1, v2 = lo2, v3 = lo3;
            if (kk == 0) {
                v0 += g_gc[c + 0]; v1 += g_gc[c + 1];
                v2 += g_gc[c + 2]; v3 += g_gc[c + 3];
            }
            *(float4*)(O + (size_t)r0 * DOUT + c) = make_float4(v0, v1, v2, v3);
        }
        if (r0 + 1 < M) {
            float v0 = hi0, v1 = hi1, v2 = hi2, v3 = hi3;
            if (kk == 0) {
                v0 += g_gc[c + 0]; v1 += g_gc[c + 1];
                v2 += g_gc[c + 2]; v3 += g_gc[c + 3];
            }
            *(float4*)(O + (size_t)(r0 + 1) * DOUT + c) = make_float4(v0, v1, v2, v3);
        }
    }
}

// ================= kernels =================

__global__ void k_setup(const int* __restrict__ ei32, int n32, int M) {
    int b = blockIdx.x;
    int nz = (M + 255) / 256;
    int tot = KMAX * D * D;
    int ni = (tot + KMAX * D + 255) / 256;

    if (b < nz) {
        int i = b * 256 + threadIdx.x;
        if (i < M) g_cnt[i] = 0;
        return;
    }
    b -= nz;
    if (b < ni) {
        int i = b * 256 + threadIdx.x;
        if (i < tot) {
            int k = i / (D * D);
            int r = i % (D * D);
            ((float*)g_Ma)[i] = (k == 0 && (r / D) == (r % D)) ? 1.f : 0.f;
        } else if (i < tot + KMAX * D) {
            ((float*)g_bA)[i - tot] = 0.f;
        }
        return;
    }
    __shared__ int any;
    if (threadIdx.x == 0) any = 0;
    __syncthreads();
    for (int i = threadIdx.x; i < 2048; i += blockDim.x) {
        int idx = 2 * i + 1;
        if (idx < n32 && ei32[idx] != 0) any = 1;
    }
    __syncthreads();
    if (threadIdx.x == 0) g_is64 = (any == 0) ? 1 : 0;
}

__global__ __launch_bounds__(256) void k_stage_prep(
    int split, int l, const float* Min, float* Mout,
    const float* Wr, const float* Wt, const float* bin, float* bout,
    const float* bl, const int* ei32, int nE, int M)
{
    if ((int)blockIdx.x < split) stage_body(blockIdx.x, l, Min, Mout, Wr, Wt, bin, bout, bl);
    else                         prep_body(blockIdx.x - split, ei32, nE, M);
}

__global__ __launch_bounds__(256) void k_stage_scan1(
    int split, int l, const float* Min, float* Mout,
    const float* Wr, const float* Wt, const float* bin, float* bout,
    const float* bl, int M)
{
    if ((int)blockIdx.x < split) stage_body(blockIdx.x, l, Min, Mout, Wr, Wt, bin, bout, bl);
    else                         scan1_body(blockIdx.x - split, M);
}

__global__ __launch_bounds__(256) void k_stage_scan2(
    int split, int l, const float* Min, float* Mout,
    const float* Wr, const float* Wt, const float* bin, float* bout,
    const float* bl, int nB)
{
    if ((int)blockIdx.x < split) stage_body(blockIdx.x, l, Min, Mout, Wr, Wt, bin, bout, bl);
    else                         scan2_body(nB);
}

__global__ __launch_bounds__(256) void k_makeC_scan3(
    int split, int L, const float* M3, const float* fcw,
    const float* b3, const float* fcb, int M, int nE)
{
    if ((int)blockIdx.x < split) makeC_body(blockIdx.x, L, M3, fcw, b3, fcb);
    else                         scan3_body(blockIdx.x - split, M, nE);
}

__global__ __launch_bounds__(256, 2) void k_proj_fill(
    int split, int gemmB, const float* x, float* out, int M, int nE)
{
    if ((int)blockIdx.x < split) {
        int kk   = blockIdx.x / gemmB;
        int tile = blockIdx.x % gemmB;
        proj_body(tile, kk, x, out, M);
    } else {
        fill_body(blockIdx.x - split, nE);
    }
}

__global__ __launch_bounds__(256) void k_agg_d2(
    int split, const float* src, float* dst, int M)
{
    if ((int)blockIdx.x < split) agg_body(blockIdx.x, src, dst, M);
    else                         d2_body(blockIdx.x - split, M);
}

__global__ __launch_bounds__(256) void k_agg_deg(
    int split, const float* src, float* dst, float* out, int M)
{
    if ((int)blockIdx.x < split) agg_body(blockIdx.x, src, dst, M);
    else                         degadd_body(blockIdx.x - split, out, M);
}

// ---------------- host orchestration ----------------
extern "C" void kernel_launch(void* const* d_in, const int* in_sizes, int n_in,
                              void* d_out, int out_size)
{
    const float* x      = (const float*)d_in[0];
    const int*   ei32   = (const int*)d_in[1];
    const float* W_rel  = (const float*)d_in[2];
    const float* b_rel  = (const float*)d_in[3];
    const float* W_root = (const float*)d_in[4];
    const float* fc_w   = (const float*)d_in[5];
    const float* fc_b   = (const float*)d_in[6];
    float*       out    = (float*)d_out;

    int M  = in_sizes[0] / D;
    int nE = in_sizes[1] / 2;
    int L  = in_sizes[2] / (D * D);
    if (M > NN_MAX) M = NN_MAX;
    if (nE > NE_MAX) nE = NE_MAX;
    if (L > L_MAX) L = L_MAX;

    float *Ma, *Mb, *bA, *bB, *Vbase, *d1v;
    cudaGetSymbolAddress((void**)&Ma, g_Ma);
    cudaGetSymbolAddress((void**)&Mb, g_Mb);
    cudaGetSymbolAddress((void**)&bA, g_bA);
    cudaGetSymbolAddress((void**)&bB, g_bB);
    cudaGetSymbolAddress((void**)&Vbase, g_V);
    cudaGetSymbolAddress((void**)&d1v, g_d1);

    int nz = (M + 255) / 256;
    int ni = (KMAX * D * D + KMAX * D + 255) / 256;
    int prepB = (nE + 255) / 256;
    int nB    = (M + SCAN_BLK - 1) / SCAN_BLK;
    int nodeB = (M + 255) / 256;
    int gemmB = (M + 127) / 128;
    int aggB  = (M + 15) / 16;

    const float* Wr1 = W_rel;
    const float* Wt1 = W_root;
    float* V1 = Vbase + 0 * (size_t)NN_MAX * DOUT;
    float* V2 = Vbase + 1 * (size_t)NN_MAX * DOUT;
    float* V3 = Vbase + 2 * (size_t)NN_MAX * DOUT;

    k_setup<<<nz + ni + 1, 256>>>(ei32, in_sizes[1], M);

    if (L == 3) {
        // pipelined: recurrence hidden under CSR build, d2/degadd hidden under big passes
        k_stage_prep <<<18 + prepB, 256>>>(18, 1, Ma, Mb, Wr1, Wt1, bA, bB,
                                           b_rel, ei32, nE, M);
        k_stage_scan1<<<27 + nB, 256>>>(27, 2, Mb, Ma,
                                        W_rel + (size_t)1 * D * D, W_root + (size_t)1 * D * D,
                                        bB, bA, b_rel + D, M);
        k_stage_scan2<<<36 + 1, 256>>>(36, 3, Ma, Mb,
                                       W_rel + (size_t)2 * D * D, W_root + (size_t)2 * D * D,
                                       bA, bB, b_rel + 2 * D, nB);
        k_makeC_scan3<<<5 * 4 + nodeB, 256>>>(5 * 4, L, Mb, fc_w, bB, fc_b, M, nE);
        k_proj_fill  <<<gemmB * 4 + prepB, 256>>>(gemmB * 4, gemmB, x, out, M, nE);
        k_agg_d2     <<<aggB + nodeB, 256>>>(aggB, V3, V2, M);
        k_agg_deg    <<<aggB + aggB, 256>>>(aggB, V2, V1, out, M);
        k_agg_d2     <<<aggB, 256>>>(aggB, V1, out, M);        // d2 part: zero blocks
    } else {
        // generic fallback: sequential, one part per launch
        k_stage_prep<<<prepB, 256>>>(0, 1, Ma, Mb, Wr1, Wt1, bA, bB, b_rel, ei32, nE, M);
        const float* Min = Ma;  float* Mout = Mb;
        const float* bin = bA;  float* bout = bB;
        for (int l = 1; l <= L; ++l) {
            k_stage_prep<<<9 * (l + 1), 256>>>(9 * (l + 1), l, Min, Mout,
                                               W_rel + (size_t)(l - 1) * D * D,
                                               W_root + (size_t)(l - 1) * D * D,
                                               bin, bout, b_rel + (size_t)(l - 1) * D,
                                               ei32, 0, M);
            const float* t1 = Min; Min = Mout; Mout = (float*)t1;
            const float* t2 = bin; bin = bout; bout = (float*)t2;
        }
        k_stage_scan1<<<nB, 256>>>(0, 1, Ma, Mb, Wr1, Wt1, bA, bB, b_rel, M);
        k_stage_scan2<<<1, 256>>>(0, 1, Ma, Mb, Wr1, Wt1, bA, bB, b_rel, nB);
        k_makeC_scan3<<<nodeB, 256>>>(0, L, Min, fc_w, bin, fc_b, M, nE);
        k_makeC_scan3<<<5 * (L + 1), 256>>>(5 * (L + 1), L, Min, fc_w, bin, fc_b, M, nE);
        k_proj_fill<<<prepB, 256>>>(0, 1, x, out, M, nE);
        k_proj_fill<<<gemmB * (L + 1), 256>>>(gemmB * (L + 1), gemmB, x, out, M, nE);
        k_agg_d2<<<nodeB, 256>>>(0, V1, out, M);               // d2 only
        for (int k = L; k >= 1; --k) {
            const float* s = Vbase + (size_t)(k - 1) * NN_MAX * DOUT;
            float*       t = (k == 1) ? out : (Vbase + (size_t)(k - 2) * NN_MAX * DOUT);
            k_agg_d2<<<aggB, 256>>>(aggB, s, t, M);
        }
        k_agg_deg<<<aggB, 256>>>(0, V1, out, out, M);          // degadd only
    }
}

// round 14
// speedup vs baseline: 1.0289x; 1.0176x over previous
#include <cuda_runtime.h>
#include <cstdint>
#include <cstddef>

#define D        128
#define DOUT     64
#define NN_MAX   100000
#define NE_MAX   1600000
#define L_MAX    3
#define KMAX     (L_MAX + 1)
#define SCAN_BLK 256
#define NB_MAX   ((NN_MAX + SCAN_BLK - 1) / SCAN_BLK)   // 391

#define PROJ_SMEM ((D * 128 + D * DOUT) * 4)            // 96 KB: A tile + B tile

// ---------------- scratch (static device globals; no allocation) ----------------
__device__ __align__(256) float g_V [L_MAX][(size_t)NN_MAX * DOUT];
__device__ __align__(256) float g_d1[NN_MAX];
__device__ __align__(256) float g_d2[NN_MAX];
__device__ __align__(256) float g_Ma[KMAX][D * D];
__device__ __align__(256) float g_Mb[KMAX][D * D];
__device__ __align__(256) float g_bA[KMAX][D];
__device__ __align__(256) float g_bB[KMAX][D];
__device__ __align__(256) float g_C [KMAX][D * DOUT];
__device__ __align__(256) float g_gc[DOUT];
__device__ __align__(256) float g_g1[DOUT];
__device__ __align__(256) float g_g2[DOUT];
__device__ __align__(256) int   g_src [NE_MAX];
__device__ __align__(256) int   g_dst [NE_MAX];
__device__ __align__(256) int   g_csr [NE_MAX];
__device__ __align__(256) int   g_ptr [NN_MAX + 1];
__device__ __align__(256) int   g_cur [NN_MAX];
__device__ __align__(256) int   g_cnt [NN_MAX];
__device__ __align__(256) int   g_bsum[NB_MAX];
__device__ int g_is64;

// ---------------- f32x2 packed-FMA helpers (Blackwell FFMA2) ----------------
__device__ __forceinline__ unsigned long long pack2(float lo, float hi) {
    unsigned long long r;
    asm("mov.b64 %0, {%1, %2};" : "=l"(r) : "f"(lo), "f"(hi));
    return r;
}
__device__ __forceinline__ void unpack2(unsigned long long v, float& lo, float& hi) {
    asm("mov.b64 {%0, %1}, %2;" : "=f"(lo), "=f"(hi) : "l"(v));
}
__device__ __forceinline__ void fma2(unsigned long long& acc, unsigned long long a,
                                     unsigned long long b) {
    asm("fma.rn.f32x2 %0, %1, %2, %0;" : "+l"(acc) : "l"(a), "l"(b));
}

// ================= device bodies (composed by merged kernels) =================

__device__ void prep_body(int pid, const int* __restrict__ ei32, int nE, int M) {
    int i = pid * 256 + threadIdx.x;
    if (i >= nE) return;
    int s, d;
    if (g_is64) {
        const long long* e = (const long long*)ei32;
        s = (int)e[i];
        d = (int)e[i + (size_t)nE];
    } else {
        s = ei32[i];
        d = ei32[i + (size_t)nE];
    }
    if (s < 0) s = 0; if (s >= M) s = M - 1;
    if (d < 0) d = 0; if (d >= M) d = M - 1;
    g_src[i] = s;
    g_dst[i] = d;
    atomicAdd(&g_cnt[d], 1);
}

__device__ void scan1_body(int bid, int M) {
    __shared__ int sh[SCAN_BLK];
    int i = bid * SCAN_BLK + threadIdx.x;
    int v = (i < M) ? g_cnt[i] : 0;
    sh[threadIdx.x] = v;
    __syncthreads();
#pragma unroll
    for (int off = 1; off < SCAN_BLK; off <<= 1) {
        int t = (threadIdx.x >= off) ? sh[threadIdx.x - off] : 0;
        __syncthreads();
        sh[threadIdx.x] += t;
        __syncthreads();
    }
    if (i < M) g_ptr[i] = sh[threadIdx.x] - v;
    if (threadIdx.x == SCAN_BLK - 1) g_bsum[bid] = sh[threadIdx.x];
}

// single block, warp-serial scan over nB block sums (exclusive)
__device__ void scan2_body(int nB) {
    if (threadIdx.x >= 32) return;
    int lane = threadIdx.x;
    int carry = 0;
    int nCh = (nB + 31) / 32;
    for (int c = 0; c < nCh; ++c) {
        int idx = c * 32 + lane;
        int v = (idx < nB) ? g_bsum[idx] : 0;
        int incl = v;
#pragma unroll
        for (int off = 1; off < 32; off <<= 1) {
            int t = __shfl_up_sync(0xFFFFFFFFu, incl, off);
            if (lane >= off) incl += t;
        }
        int total = __shfl_sync(0xFFFFFFFFu, incl, 31);
        if (idx < nB) g_bsum[idx] = incl - v + carry;
        carry += total;
    }
}

__device__ void scan3_body(int bid, int M, int nE) {
    int i = bid * 256 + threadIdx.x;
    if (i < M) {
        int p = g_ptr[i] + g_bsum[i / SCAN_BLK];
        g_ptr[i] = p;
        g_cur[i] = p;
        g_d1[i] = (float)g_cnt[i];
    }
    if (i == 0) g_ptr[M] = nE;
}

__device__ void fill_body(int bid, int nE) {
    int i = bid * 256 + threadIdx.x;
    if (i >= nE) return;
    int slot = atomicAdd(&g_cur[g_dst[i]], 1);
    g_csr[slot] = g_src[i];
}

__device__ void d2_body(int bid, int M) {
    int i = bid * 256 + threadIdx.x;
    if (i >= M) return;
    int beg = g_ptr[i], end = g_ptr[i + 1];
    float s = 0.f;
    int e = beg;
    for (; e + 4 <= end; e += 4) {
        float a = g_d1[g_csr[e + 0]];
        float b = g_d1[g_csr[e + 1]];
        float c = g_d1[g_csr[e + 2]];
        float d = g_d1[g_csr[e + 3]];
        s += (a + b) + (c + d);
    }
    for (; e < end; ++e) s += g_d1[g_csr[e]];
    g_d2[i] = s;
}

__device__ void agg_body(int bid, const float* __restrict__ src,
                         float* __restrict__ dst, int M) {
    int node = bid * 16 + (threadIdx.x >> 4);
    int l16  = threadIdx.x & 15;
    if (node >= M) return;
    int beg = g_ptr[node], end = g_ptr[node + 1];

    float4 acc = *(const float4*)(dst + (size_t)node * DOUT + l16 * 4);
    int e = beg;
    for (; e + 4 <= end; e += 4) {
        int s0 = g_csr[e], s1 = g_csr[e + 1], s2 = g_csr[e + 2], s3 = g_csr[e + 3];
        float4 v0 = *(const float4*)(src + (size_t)s0 * DOUT + l16 * 4);
        float4 v1 = *(const float4*)(src + (size_t)s1 * DOUT + l16 * 4);
        float4 v2 = *(const float4*)(src + (size_t)s2 * DOUT + l16 * 4);
        float4 v3 = *(const float4*)(src + (size_t)s3 * DOUT + l16 * 4);
        acc.x += (v0.x + v1.x) + (v2.x + v3.x);
        acc.y += (v0.y + v1.y) + (v2.y + v3.y);
        acc.z += (v0.z + v1.z) + (v2.z + v3.z);
        acc.w += (v0.w + v1.w) + (v2.w + v3.w);
    }
    for (; e < end; ++e) {
        int s0 = g_csr[e];
        float4 v0 = *(const float4*)(src + (size_t)s0 * DOUT + l16 * 4);
        acc.x += v0.x; acc.y += v0.y; acc.z += v0.z; acc.w += v0.w;
    }
    *(float4*)(dst + (size_t)node * DOUT + l16 * 4) = acc;
}

__device__ void degadd_body(int bid, float* __restrict__ out, int M) {
    int node = bid * 16 + (threadIdx.x >> 4);
    if (node >= M) return;
    int c = (threadIdx.x & 15) * 4;
    float dd1 = g_d1[node], dd2 = g_d2[node];
    float4 o = *(float4*)(out + (size_t)node * DOUT + c);
    o.x += dd1 * g_g1[c + 0] + dd2 * g_g2[c + 0];
    o.y += dd1 * g_g1[c + 1] + dd2 * g_g2[c + 1];
    o.z += dd1 * g_g1[c + 2] + dd2 * g_g2[c + 2];
    o.w += dd1 * g_g1[c + 3] + dd2 * g_g2[c + 3];
    *(float4*)(out + (size_t)node * DOUT + c) = o;
}

// stage sb in [0, 9*(l+1)): k = sb % (l+1), sx = sb / (l+1); sx==8 -> beta (k==0 only)
__device__ void stage_body(int sb, int l,
                           const float* __restrict__ Min, float* __restrict__ Mout,
                           const float* __restrict__ Wr, const float* __restrict__ Wt,
                           const float* __restrict__ bin, float* __restrict__ bout,
                           const float* __restrict__ bl)
{
    const int tid = threadIdx.x;
    const int k   = sb % (l + 1);
    const int sx  = sb / (l + 1);

    if (sx == 8) {
        if (k != 0) return;
        __shared__ float sbeta[L_MAX + 1][D];
        int n = tid;
        if (n < D) {
#pragma unroll
            for (int kk = 0; kk < L_MAX; ++kk)
                sbeta[kk][n] = (kk <= l - 2) ? bin[kk * D + n] : 0.f;
            sbeta[L_MAX][n] = 0.f;
        }
        __syncthreads();
        if (n < D) {
            for (int kk = 0; kk < l; ++kk) {
                const float* tp = sbeta[kk];
                const float* rp = (kk >= 1) ? sbeta[kk - 1] : sbeta[L_MAX];
                float acc = (kk == 0) ? bl[n] : 0.f;
#pragma unroll 4
                for (int q4 = 0; q4 < 32; ++q4) {
                    float4 wt = *(const float4*)&Wt[(size_t)n * D + q4 * 4];
                    float4 wr = *(const float4*)&Wr[(size_t)n * D + q4 * 4];
                    acc += wt.x * tp[q4 * 4 + 0] + wt.y * tp[q4 * 4 + 1]
                         + wt.z * tp[q4 * 4 + 2] + wt.w * tp[q4 * 4 + 3]
                         + wr.x * rp[q4 * 4 + 0] + wr.y * rp[q4 * 4 + 1]
                         + wr.z * rp[q4 * 4 + 2] + wr.w * rp[q4 * 4 + 3];
                }
                bout[kk * D + n] = acc;
            }
        }
        return;
    }

    __shared__ float sT[32][132];
    __shared__ float sR[32][132];
    __shared__ float sWt[64][16];
    __shared__ float sWr[64][16];

    const int p0 = (sx >> 1) * 32;
    const int nh = (sx & 1) * 64;

    const bool vT = (k <= l - 1);
    const bool vR = (k >= 1);
    for (int i = tid * 4; i < 32 * 128; i += 1024) {
        int p = i >> 7, q = i & 127;
        float4 t = vT ? *(const float4*)&Min[(size_t)k * D * D + (p0 + p) * D + q]
                      : make_float4(0.f, 0.f, 0.f, 0.f);
        float4 r = vR ? *(const float4*)&Min[(size_t)(k - 1) * D * D + (p0 + p) * D + q]
                      : make_float4(0.f, 0.f, 0.f, 0.f);
        *(float4*)&sT[p][q] = t;
        *(float4*)&sR[p][q] = r;
    }

    const int p  = tid & 31;
    const int nl = (tid >> 5) * 8;
    const int wn = (tid * 4) >> 4;
    const int wq = (tid * 4) & 15;
    float acc[8] = {0.f, 0.f, 0.f, 0.f, 0.f, 0.f, 0.f, 0.f};

    float4 wtp = *(const float4*)&Wt[(size_t)(nh + wn) * D + 0 + wq];
    float4 wrp = *(const float4*)&Wr[(size_t)(nh + wn) * D + 0 + wq];

#pragma unroll 1
    for (int qt = 0; qt < 8; ++qt) {
        int q0 = qt * 16;
        __syncthreads();
        *(float4*)&sWt[wn][wq] = wtp;
        *(float4*)&sWr[wn][wq] = wrp;
        __syncthreads();
        if (qt + 1 < 8) {
            int qn = (qt + 1) * 16;
            wtp = *(const float4*)&Wt[(size_t)(nh + wn) * D + qn + wq];
            wrp = *(const float4*)&Wr[(size_t)(nh + wn) * D + qn + wq];
        }
#pragma unroll
        for (int q4 = 0; q4 < 4; ++q4) {
            float4 t = *(const float4*)&sT[p][q0 + q4 * 4];
            float4 r = *(const float4*)&sR[p][q0 + q4 * 4];
#pragma unroll
            for (int n = 0; n < 8; ++n) {
                float4 wt = *(const float4*)&sWt[nl + n][q4 * 4];
                float4 wr = *(const float4*)&sWr[nl + n][q4 * 4];
                acc[n] += t.x * wt.x + t.y * wt.y + t.z * wt.z + t.w * wt.w
                        + r.x * wr.x + r.y * wr.y + r.z * wr.z + r.w * wr.w;
            }
        }
    }

#pragma unroll
    for (int n = 0; n < 8; ++n)
        Mout[(size_t)k * D * D + (p0 + p) * D + (nh + nl + n)] = acc[n];
}

// makeC sb in [0, 5*(L+1)): ky = sb % (L+1), bx = sb / (L+1); bx==4 -> gamma (ky==0)
__device__ void makeC_body(int sb, int L,
                           const float* __restrict__ M3, const float* __restrict__ fcw,
                           const float* __restrict__ b3, const float* __restrict__ fcb)
{
    const int tid = threadIdx.x;
    const int ky  = sb % (L + 1);
    const int bx  = sb / (L + 1);

    if (bx == 4) {
        if (ky != 0 || tid >= DOUT) return;
        int n = tid;
        float a0 = fcb[n], a1 = 0.f, a2 = 0.f;
#pragma unroll 4
        for (int q4 = 0; q4 < 32; ++q4) {
            float4 w = *(const float4*)&fcw[(size_t)n * D + q4 * 4];
            float4 v0 = *(const float4*)&b3[0 * D + q4 * 4];
            a0 += w.x * v0.x + w.y * v0.y + w.z * v0.z + w.w * v0.w;
            if (L >= 2) {
                float4 v1 = *(const float4*)&b3[1 * D + q4 * 4];
                a1 += w.x * v1.x + w.y * v1.y + w.z * v1.z + w.w * v1.w;
            }
            if (L >= 3) {
                float4 v2 = *(const float4*)&b3[2 * D + q4 * 4];
                a2 += w.x * v2.x + w.y * v2.y + w.z * v2.z + w.w * v2.w;
            }
        }
        g_gc[n] = a0; g_g1[n] = a1; g_g2[n] = a2;
        return;
    }

    __shared__ float sM[32][132];
    __shared__ float sW[64][16];
    const int k  = ky;
    const int p0 = bx * 32;

    for (int i = tid * 4; i < 32 * 128; i += 1024) {
        int p = i >> 7, q = i & 127;
        *(float4*)&sM[p][q] = *(const float4*)&M3[(size_t)k * D * D + (p0 + p) * D + q];
    }

    const int p  = tid & 31;
    const int nl = (tid >> 5) * 8;
    const int wn = (tid * 4) >> 4;
    const int wq = (tid * 4) & 15;
    float acc[8] = {0.f, 0.f, 0.f, 0.f, 0.f, 0.f, 0.f, 0.f};

    float4 wp = *(const float4*)&fcw[(size_t)wn * D + 0 + wq];

#pragma unroll 1
    for (int qt = 0; qt < 8; ++qt) {
        int q0 = qt * 16;
        __syncthreads();
        *(float4*)&sW[wn][wq] = wp;
        __syncthreads();
        if (qt + 1 < 8) {
            int qn = (qt + 1) * 16;
            wp = *(const float4*)&fcw[(size_t)wn * D + qn + wq];
        }
#pragma unroll
        for (int q4 = 0; q4 < 4; ++q4) {
            float4 m = *(const float4*)&sM[p][q0 + q4 * 4];
#pragma unroll
            for (int n = 0; n < 8; ++n) {
                float4 w = *(const float4*)&sW[nl + n][q4 * 4];
                acc[n] += m.x * w.x + m.y * w.y + m.z * w.z + m.w * w.w;
            }
        }
    }
#pragma unroll
    for (int n = 0; n < 8; ++n)
        g_C[k][(p0 + p) * DOUT + nl + n] = acc[n];
}

// projection tile with FULL A tile staged in dynamic smem (no per-slab syncs).
// smem layout: As[k][row] (k-major, 64 KB) | Bs[k][n] (32 KB).
// Same accumulation order as R11 -> bit-identical result.
__device__ void proj_body(int tile, int kk, const float* __restrict__ A,
                          float* __restrict__ out, int M, float* smem)
{
    float* As = smem;             // [128 k][128 row]
    float* Bs = smem + D * 128;   // [128 k][64 n]

    float* O = (kk == 0) ? out : &g_V[kk - 1][0];
    const float* B = &g_C[kk][0];

    const int tid  = threadIdx.x;
    const int trow = tid >> 4;
    const int tcol = tid & 15;
    const int block_row = tile * 128;

#pragma unroll
    for (int v = 0; v < 8; ++v) {
        int o = v * 1024 + tid * 4;
        *(float4*)&Bs[o] = *(const float4*)&B[o];
    }

    const int arow = tid >> 1;
    const int akk  = (tid & 1) << 2;
    int grow = block_row + arow;
    if (grow >= M) grow = M - 1;
    const float* xr = A + (size_t)grow * D;

    // stage entire A tile: 16 slabs, no syncs between -> deep LDG MLP
#pragma unroll 4
    for (int s = 0; s < 16; ++s) {
        int kb = s * 8 + akk;
        float4 a = *(const float4*)(xr + kb);
        As[(kb + 0) * 128 + arow] = a.x;
        As[(kb + 1) * 128 + arow] = a.y;
        As[(kb + 2) * 128 + arow] = a.z;
        As[(kb + 3) * 128 + arow] = a.w;
    }

    unsigned long long acc[4][4];
#pragma unroll
    for (int i = 0; i < 4; i++)
#pragma unroll
        for (int j = 0; j < 4; j++) acc[i][j] = 0ull;

    __syncthreads();

#pragma unroll 8
    for (int k = 0; k < D; ++k) {
        ulonglong2 a01 = *(const ulonglong2*)&As[k * 128 + trow * 8];
        ulonglong2 a23 = *(const ulonglong2*)&As[k * 128 + trow * 8 + 4];
        float4 b = *(const float4*)&Bs[k * DOUT + tcol * 4];
        unsigned long long b0 = pack2(b.x, b.x);
        unsigned long long b1 = pack2(b.y, b.y);
        unsigned long long b2 = pack2(b.z, b.z);
        unsigned long long b3 = pack2(b.w, b.w);
        fma2(acc[0][0], a01.x, b0); fma2(acc[0][1], a01.x, b1);
        fma2(acc[0][2], a01.x, b2); fma2(acc[0][3], a01.x, b3);
        fma2(acc[1][0], a01.y, b0); fma2(acc[1][1], a01.y, b1);
        fma2(acc[1][2], a01.y, b2); fma2(acc[1][3], a01.y, b3);
        fma2(acc[2][0], a23.x, b0); fma2(acc[2][1], a23.x, b1);
        fma2(acc[2][2], a23.x, b2); fma2(acc[2][3], a23.x, b3);
        fma2(acc[3][0], a23.y, b0); fma2(acc[3][1], a23.y, b1);
        fma2(acc[3][2], a23.y, b2); fma2(acc[3][3], a23.y, b3);
    }

#pragma unroll
    for (int rp = 0; rp < 4; ++rp) {
        float lo0, hi0, lo1, hi1, lo2, hi2, lo3, hi3;
        unpack2(acc[rp][0], lo0, hi0);
        unpack2(acc[rp][1], lo1, hi1);
        unpack2(acc[rp][2], lo2, hi2);
        unpack2(acc[rp][3], lo3, hi3);
        int r0 = block_row + trow * 8 + 2 * rp;
        int c  = tcol * 4;
        if (r0 < M) {
            float v0 = lo0, v1 = lo1, v2 = lo2, v3 = lo3;
            if (kk == 0) {
                v0 += g_gc[c + 0]; v1 += g_gc[c + 1];
                v2 += g_gc[c + 2]; v3 += g_gc[c + 3];
            }
            *(float4*)(O + (size_t)r0 * DOUT + c) = make_float4(v0, v1, v2, v3);
        }
        if (r0 + 1 < M) {
            float v0 = hi0, v1 = hi1, v2 = hi2, v3 = hi3;
            if (kk == 0) {
                v0 += g_gc[c + 0]; v1 += g_gc[c + 1];
                v2 += g_gc[c + 2]; v3 += g_gc[c + 3];
            }
            *(float4*)(O + (size_t)(r0 + 1) * DOUT + c) = make_float4(v0, v1, v2, v3);
        }
    }
}

// ================= kernels =================

__global__ void k_setup(const int* __restrict__ ei32, int n32, int M) {
    int b = blockIdx.x;
    int nz = (M + 255) / 256;
    int tot = KMAX * D * D;
    int ni = (tot + KMAX * D + 255) / 256;

    if (b < nz) {
        int i = b * 256 + threadIdx.x;
        if (i < M) g_cnt[i] = 0;
        return;
    }
    b -= nz;
    if (b < ni) {
        int i = b * 256 + threadIdx.x;
        if (i < tot) {
            int k = i / (D * D);
            int r = i % (D * D);
            ((float*)g_Ma)[i] = (k == 0 && (r / D) == (r % D)) ? 1.f : 0.f;
        } else if (i < tot + KMAX * D) {
            ((float*)g_bA)[i - tot] = 0.f;
        }
        return;
    }
    __shared__ int any;
    if (threadIdx.x == 0) any = 0;
    __syncthreads();
    for (int i = threadIdx.x; i < 2048; i += blockDim.x) {
        int idx = 2 * i + 1;
        if (idx < n32 && ei32[idx] != 0) any = 1;
    }
    __syncthreads();
    if (threadIdx.x == 0) g_is64 = (any == 0) ? 1 : 0;
}

__global__ __launch_bounds__(256) void k_stage_prep(
    int split, int l, const float* Min, float* Mout,
    const float* Wr, const float* Wt, const float* bin, float* bout,
    const float* bl, const int* ei32, int nE, int M)
{
    if ((int)blockIdx.x < split) stage_body(blockIdx.x, l, Min, Mout, Wr, Wt, bin, bout, bl);
    else                         prep_body(blockIdx.x - split, ei32, nE, M);
}

__global__ __launch_bounds__(256) void k_stage_scan1(
    int split, int l, const float* Min, float* Mout,
    const float* Wr, const float* Wt, const float* bin, float* bout,
    const float* bl, int M)
{
    if ((int)blockIdx.x < split) stage_body(blockIdx.x, l, Min, Mout, Wr, Wt, bin, bout, bl);
    else                         scan1_body(blockIdx.x - split, M);
}

__global__ __launch_bounds__(256) void k_stage_scan2(
    int split, int l, const float* Min, float* Mout,
    const float* Wr, const float* Wt, const float* bin, float* bout,
    const float* bl, int nB)
{
    if ((int)blockIdx.x < split) stage_body(blockIdx.x, l, Min, Mout, Wr, Wt, bin, bout, bl);
    else                         scan2_body(nB);
}

__global__ __launch_bounds__(256) void k_makeC_scan3(
    int split, int L, const float* M3, const float* fcw,
    const float* b3, const float* fcb, int M, int nE)
{
    if ((int)blockIdx.x < split) makeC_body(blockIdx.x, L, M3, fcw, b3, fcb);
    else                         scan3_body(blockIdx.x - split, M, nE);
}

__global__ __launch_bounds__(256, 2) void k_proj_fill(
    int split, int gemmB, const float* x, float* out, int M, int nE)
{
    extern __shared__ float proj_smem[];
    if ((int)blockIdx.x < split) {
        int kk   = blockIdx.x / gemmB;
        int tile = blockIdx.x % gemmB;
        proj_body(tile, kk, x, out, M, proj_smem);
    } else {
        fill_body(blockIdx.x - split, nE);
    }
}

__global__ __launch_bounds__(256) void k_agg_d2(
    int split, const float* src, float* dst, int M)
{
    if ((int)blockIdx.x < split) agg_body(blockIdx.x, src, dst, M);
    else                         d2_body(blockIdx.x - split, M);
}

__global__ __launch_bounds__(256) void k_agg_deg(
    int split, const float* src, float* dst, float* out, int M)
{
    if ((int)blockIdx.x < split) agg_body(blockIdx.x, src, dst, M);
    else                         degadd_body(blockIdx.x - split, out, M);
}

// ---------------- host orchestration ----------------
extern "C" void kernel_launch(void* const* d_in, const int* in_sizes, int n_in,
                              void* d_out, int out_size)
{
    const float* x      = (const float*)d_in[0];
    const int*   ei32   = (const int*)d_in[1];
    const float* W_rel  = (const float*)d_in[2];
    const float* b_rel  = (const float*)d_in[3];
    const float* W_root = (const float*)d_in[4];
    const float* fc_w   = (const float*)d_in[5];
    const float* fc_b   = (const float*)d_in[6];
    float*       out    = (float*)d_out;

    int M  = in_sizes[0] / D;
    int nE = in_sizes[1] / 2;
    int L  = in_sizes[2] / (D * D);
    if (M > NN_MAX) M = NN_MAX;
    if (nE > NE_MAX) nE = NE_MAX;
    if (L > L_MAX) L = L_MAX;

    float *Ma, *Mb, *bA, *bB, *Vbase;
    cudaGetSymbolAddress((void**)&Ma, g_Ma);
    cudaGetSymbolAddress((void**)&Mb, g_Mb);
    cudaGetSymbolAddress((void**)&bA, g_bA);
    cudaGetSymbolAddress((void**)&bB, g_bB);
    cudaGetSymbolAddress((void**)&Vbase, g_V);

    cudaFuncSetAttribute(k_proj_fill, cudaFuncAttributeMaxDynamicSharedMemorySize,
                         PROJ_SMEM);

    int nz = (M + 255) / 256;
    int ni = (KMAX * D * D + KMAX * D + 255) / 256;
    int prepB = (nE + 255) / 256;
    int nB    = (M + SCAN_BLK - 1) / SCAN_BLK;
    int nodeB = (M + 255) / 256;
    int gemmB = (M + 127) / 128;
    int aggB  = (M + 15) / 16;

    const float* Wr1 = W_rel;
    const float* Wt1 = W_root;
    float* V1 = Vbase + 0 * (size_t)NN_MAX * DOUT;
    float* V2 = Vbase + 1 * (size_t)NN_MAX * DOUT;
    float* V3 = Vbase + 2 * (size_t)NN_MAX * DOUT;

    k_setup<<<nz + ni + 1, 256>>>(ei32, in_sizes[1], M);

    if (L == 3) {
        k_stage_prep <<<18 + prepB, 256>>>(18, 1, Ma, Mb, Wr1, Wt1, bA, bB,
                                           b_rel, ei32, nE, M);
        k_stage_scan1<<<27 + nB, 256>>>(27, 2, Mb, Ma,
                                        W_rel + (size_t)1 * D * D, W_root + (size_t)1 * D * D,
                                        bB, bA, b_rel + D, M);
        k_stage_scan2<<<36 + 1, 256>>>(36, 3, Ma, Mb,
                                       W_rel + (size_t)2 * D * D, W_root + (size_t)2 * D * D,
                                       bA, bB, b_rel + 2 * D, nB);
        k_makeC_scan3<<<5 * 4 + nodeB, 256>>>(5 * 4, L, Mb, fc_w, bB, fc_b, M, nE);
        k_proj_fill  <<<gemmB * 4 + prepB, 256, PROJ_SMEM>>>(gemmB * 4, gemmB, x, out, M, nE);
        k_agg_d2     <<<aggB + nodeB, 256>>>(aggB, V3, V2, M);
        k_agg_deg    <<<aggB + aggB, 256>>>(aggB, V2, V1, out, M);
        k_agg_d2     <<<aggB, 256>>>(aggB, V1, out, M);
    } else {
        k_stage_prep<<<prepB, 256>>>(0, 1, Ma, Mb, Wr1, Wt1, bA, bB, b_rel, ei32, nE, M);
        const float* Min = Ma;  float* Mout = Mb;
        const float* bin = bA;  float* bout = bB;
        for (int l = 1; l <= L; ++l) {
            k_stage_prep<<<9 * (l + 1), 256>>>(9 * (l + 1), l, Min, Mout,
                                               W_rel + (size_t)(l - 1) * D * D,
                                               W_root + (size_t)(l - 1) * D * D,
                                               bin, bout, b_rel + (size_t)(l - 1) * D,
                                               ei32, 0, M);
            const float* t1 = Min; Min = Mout; Mout = (float*)t1;
            const float* t2 = bin; bin = bout; bout = (float*)t2;
        }
        k_stage_scan1<<<nB, 256>>>(0, 1, Ma, Mb, Wr1, Wt1, bA, bB, b_rel, M);
        k_stage_scan2<<<1, 256>>>(0, 1, Ma, Mb, Wr1, Wt1, bA, bB, b_rel, nB);
        k_makeC_scan3<<<nodeB, 256>>>(0, L, Min, fc_w, bin, fc_b, M, nE);
        k_makeC_scan3<<<5 * (L + 1), 256>>>(5 * (L + 1), L, Min, fc_w, bin, fc_b, M, nE);
        k_proj_fill<<<prepB, 256, PROJ_SMEM>>>(0, 1, x, out, M, nE);
        k_proj_fill<<<gemmB * (L + 1), 256, PROJ_SMEM>>>(gemmB * (L + 1), gemmB,
                                                         x, out, M, nE);
        k_agg_d2<<<nodeB, 256>>>(0, V1, out, M);
        for (int k = L; k >= 1; --k) {
            const float* s = Vbase + (size_t)(k - 1) * NN_MAX * DOUT;
            float*       t = (k == 1) ? out : (Vbase + (size_t)(k - 2) * NN_MAX * DOUT);
            k_agg_d2<<<aggB, 256>>>(aggB, s, t, M);
        }
        k_agg_deg<<<aggB, 256>>>(0, V1, out, out, M);
    }
}